// round 13
// baseline (speedup 1.0000x reference)
#include <cuda_runtime.h>
#include <cuda_bf16.h>
#include <cuda_fp16.h>
#include <cstdint>

#define NN 100000
#define NE 1600000
#define NG 1000
#define F  100
#define FC 25     // 4-feature chunks per row
#define SP1 352   // padded K stride for layer-1 input (336 -> 352 = 11*32)
#define SPH 128   // padded K stride for hidden layers (100 -> 128 = 4*32)
#define KP  40    // smem k-stride (bf16 elems), conflict-free
#define ARRB (128 * KP * 2)   // bytes per smem array (10240)
#define WSLOT (128 * SP1)

// ---------------- scratch ----------------
__device__ __align__(16) __half g_xwh[(size_t)NN * F];   // GEMM output, fp16
__device__ __align__(16) __nv_bfloat16 g_ah[(size_t)NN * SP1];
__device__ __align__(16) __nv_bfloat16 g_al[(size_t)NN * SP1];
__device__ __align__(16) __nv_bfloat16 g_bh[5 * 128 * SP1];
__device__ __align__(16) __nv_bfloat16 g_bl[5 * 128 * SP1];
__device__ int   g_degi[NN];
__device__ int   g_off[NN + 1];
__device__ int   g_cur[NN];
__device__ float g_dinv[NN];
__device__ float g_selfw[NN];
__device__ int   g_row[NE];
__device__ int   g_col[NE];
__device__ int   g_src[NE];
__device__ float g_wt[NE];
__device__ int   g_batch[NN];
__device__ __align__(16) float g_pool[NG * F];
__device__ float g_cnt[NG];
__device__ float g_t1[NG * F];
__device__ float g_t2[NG * F];
__device__ int   g_is64;
__device__ int   g_bsum[128];
__device__ int   g_bpre[128];

__device__ __forceinline__ void red4(float4* p, float x, float y, float z, float w) {
    asm volatile("red.global.add.v4.f32 [%0], {%1,%2,%3,%4};"
                 :: "l"(p), "f"(x), "f"(y), "f"(z), "f"(w) : "memory");
}

__device__ __forceinline__ uint32_t pk2(__nv_bfloat16 a, __nv_bfloat16 b) {
    union { __nv_bfloat162 v; uint32_t u; } c;
    c.v = __nv_bfloat162(a, b);
    return c.u;
}

// load 4 fp16 features of node row, lane-indexed, as floats
__device__ __forceinline__ float4 ldxw4(int node, int lane) {
    uint2 v = __ldg((const uint2*)(g_xwh + (size_t)node * F) + lane);
    __half2 h0 = *reinterpret_cast<__half2*>(&v.x);
    __half2 h1 = *reinterpret_cast<__half2*>(&v.y);
    float2 f0 = __half22float2(h0);
    float2 f1 = __half22float2(h1);
    return make_float4(f0.x, f0.y, f1.x, f1.y);
}

// ---------------- bf16 split preprocessing ----------------
__global__ void split_x_kernel(const float* __restrict__ x) {
    size_t i = (size_t)blockIdx.x * blockDim.x + threadIdx.x;
    if (i >= (size_t)NN * SP1) return;
    int node = (int)(i / SP1);
    int k    = (int)(i - (size_t)node * SP1);
    float v = (k < 336) ? x[(size_t)node * 336 + k] : 0.0f;
    __nv_bfloat16 hi = __float2bfloat16(v);
    g_ah[i] = hi;
    g_al[i] = __float2bfloat16(v - __bfloat162float(hi));
}

__global__ void wsplit_all_kernel(const float* __restrict__ W0, const float* __restrict__ W1,
                                  const float* __restrict__ W2, const float* __restrict__ W3,
                                  const float* __restrict__ W4) {
    int l = blockIdx.y;
    const float* W = (l == 0) ? W0 : (l == 1) ? W1 : (l == 2) ? W2 : (l == 3) ? W3 : W4;
    int SP = l ? SPH : SP1;
    int K  = l ? 100 : 336;
    int base = l * WSLOT;
    int i = blockIdx.x * blockDim.x + threadIdx.x;
    if (i >= 128 * SP) return;
    int n = i / SP;
    int k = i - n * SP;
    float v = (n < 100 && k < K) ? W[k * 100 + n] : 0.0f;
    __nv_bfloat16 hi = __float2bfloat16(v);
    g_bh[base + i] = hi;
    g_bl[base + i] = __float2bfloat16(v - __bfloat162float(hi));
}

// ---------------- dtype detection + zero-init fused ----------------
__global__ void detect_kernel(const int* __restrict__ ei32) {
    __shared__ int s;
    int t = threadIdx.x;
    if (t == 0) s = 0;
    __syncthreads();
    int v = ei32[t * 2 + 1] | ei32[2048 + t * 2 + 1] |
            ei32[4096 + t * 2 + 1] | ei32[6144 + t * 2 + 1];
    if (v) atomicOr(&s, 1);
    __syncthreads();
    if (t == 0) g_is64 = (s == 0) ? 1 : 0;
    for (int i = t; i < NN; i += 512) g_degi[i] = 0;
    for (int i = t; i < NG; i += 512) g_cnt[i] = 0.0f;
    for (int i = t; i < NG * FC; i += 512)
        ((float4*)g_pool)[i] = make_float4(0.f, 0.f, 0.f, 0.f);
}

// ---------------- graph preprocessing ----------------
__global__ void prep_deg_kernel(const void* __restrict__ ei) {
    int e = blockIdx.x * blockDim.x + threadIdx.x;
    if (e >= NE) return;
    int r, c;
    if (g_is64) {
        const long long* p = (const long long*)ei;
        r = (int)p[e];
        c = (int)p[NE + e];
    } else {
        const int* p = (const int*)ei;
        r = p[e];
        c = p[NE + e];
    }
    g_row[e] = r;
    g_col[e] = c;
    atomicAdd(&g_degi[c], 1);
}

__global__ void prep_batch_kernel(const void* __restrict__ batch) {
    int i = blockIdx.x * blockDim.x + threadIdx.x;
    if (i >= NN) return;
    int b;
    if (g_is64) b = (int)((const long long*)batch)[i];
    else        b = ((const int*)batch)[i];
    g_batch[i] = b;
    atomicAdd(&g_cnt[b], 1.0f);
}

// ---------------- coalesced 3-phase scan ----------------
__global__ void scan1_kernel() {
    __shared__ int red[32];
    int b = blockIdx.x, t = threadIdx.x;
    int idx = b * 1024 + t;
    int v = 0;
    if (idx < NN) {
        v = g_degi[idx];
        float d = (float)v + 2.0f;
        float r = rsqrtf(d);
        r = r * (1.5f - 0.5f * d * r * r);
        g_dinv[idx]  = r;
        g_selfw[idx] = 2.0f / d;
    }
    int s = v;
#pragma unroll
    for (int o = 16; o > 0; o >>= 1) s += __shfl_down_sync(~0u, s, o);
    if ((t & 31) == 0) red[t >> 5] = s;
    __syncthreads();
    if (t < 32) {
        int x = red[t];
#pragma unroll
        for (int o = 16; o > 0; o >>= 1) x += __shfl_down_sync(~0u, x, o);
        if (t == 0) g_bsum[b] = x;
    }
}

__global__ void scan2_kernel(int nblk) {
    int t = threadIdx.x;
    __shared__ int sh[128];
    int v = (t < nblk) ? g_bsum[t] : 0;
    sh[t] = v;
    __syncthreads();
    for (int o = 1; o < 128; o <<= 1) {
        int u = (t >= o) ? sh[t - o] : 0;
        __syncthreads();
        sh[t] += u;
        __syncthreads();
    }
    g_bpre[t] = sh[t] - v;
    if (t == 0) g_off[NN] = NE;
}

__global__ void scan3_kernel() {
    __shared__ int ws[32];
    int b = blockIdx.x, t = threadIdx.x;
    int idx = b * 1024 + t;
    int lane = t & 31, w = t >> 5;
    int v = (idx < NN) ? g_degi[idx] : 0;
    int s = v;
#pragma unroll
    for (int o = 1; o < 32; o <<= 1) {
        int u = __shfl_up_sync(~0u, s, o);
        if (lane >= o) s += u;
    }
    if (lane == 31) ws[w] = s;
    __syncthreads();
    if (t < 32) {
        int x = ws[t];
#pragma unroll
        for (int o = 1; o < 32; o <<= 1) {
            int u = __shfl_up_sync(~0u, x, o);
            if (t >= o) x += u;
        }
        ws[t] = x;
    }
    __syncthreads();
    if (idx < NN) {
        int excl = s - v + (w ? ws[w - 1] : 0) + g_bpre[b];
        g_off[idx] = excl;
        g_cur[idx] = excl;
    }
}

__global__ void fill_kernel() {
    int e = blockIdx.x * blockDim.x + threadIdx.x;
    if (e >= NE) return;
    int r = g_row[e];
    int c = g_col[e];
    int pos = atomicAdd(&g_cur[c], 1);
    g_src[pos] = r;
    g_wt[pos]  = g_dinv[r] * g_dinv[c];
}

// ---------------- tensor GEMM (bf16 split, cp.async x2, ldmatrix frags) -------
__device__ __forceinline__ void mma_bf16(float* d, const uint32_t* a, const uint32_t* b) {
    asm volatile(
        "mma.sync.aligned.m16n8k16.row.col.f32.bf16.bf16.f32 "
        "{%0,%1,%2,%3}, {%4,%5,%6,%7}, {%8,%9}, {%0,%1,%2,%3};"
        : "+f"(d[0]), "+f"(d[1]), "+f"(d[2]), "+f"(d[3])
        : "r"(a[0]), "r"(a[1]), "r"(a[2]), "r"(a[3]), "r"(b[0]), "r"(b[1]));
}

__device__ __forceinline__ void cpa16(uint32_t dst, const void* src, int sz) {
    asm volatile("cp.async.cg.shared.global [%0], [%1], 16, %2;"
                 :: "r"(dst), "l"(src), "r"(sz));
}

__device__ __forceinline__ void ldsm_x4(uint32_t* r, uint32_t addr) {
    asm volatile("ldmatrix.sync.aligned.m8n8.x4.shared.b16 {%0,%1,%2,%3}, [%4];"
                 : "=r"(r[0]), "=r"(r[1]), "=r"(r[2]), "=r"(r[3]) : "r"(addr));
}

__device__ __forceinline__ void ldsm_x2(uint32_t* r, uint32_t addr) {
    asm volatile("ldmatrix.sync.aligned.m8n8.x2.shared.b16 {%0,%1}, [%2];"
                 : "=r"(r[0]), "=r"(r[1]) : "r"(addr));
}

__global__ __launch_bounds__(256, 2) void sgemm_kernel(int wslot, int M, int SP)
{
    extern __shared__ __align__(16) char smem[];
    const __nv_bfloat16* __restrict__ Ahg = g_ah;
    const __nv_bfloat16* __restrict__ Alg = g_al;
    const __nv_bfloat16* __restrict__ Bhg = g_bh + wslot;
    const __nv_bfloat16* __restrict__ Blg = g_bl + wslot;

    const int steps = SP / 32;
    int t     = threadIdx.x;
    int m_blk = blockIdx.x * 128;
    int wid   = t >> 5, lane = t & 31;
    int wm    = wid >> 2;
    int wn    = wid & 3;
    int lr    = lane >> 2;
    int lc2   = (lane & 3) << 1;
    uint32_t sbase = (uint32_t)__cvta_generic_to_shared(smem);

    int aRow  = lane & 15;
    int aCol8 = (lane >> 4) << 3;
    int bRow  = lane & 7;
    int bCol8 = lane & 8;

    float acc[4][4][4];
#pragma unroll
    for (int i = 0; i < 4; i++)
#pragma unroll
        for (int j = 0; j < 4; j++)
#pragma unroll
            for (int q = 0; q < 4; q++) acc[i][j][q] = 0.0f;

    auto issue = [&](int s, int buf) {
        int k0 = s * 32;
        uint32_t b = sbase + buf * 4 * ARRB;
#pragma unroll
        for (int i = 0; i < 2; i++) {
            int c   = t + 256 * i;
            int row = c >> 2;
            int ch  = c & 3;
            uint32_t doff = row * (KP * 2) + ch * 16;
            int gm  = m_blk + row;
            int gmc = (gm < M) ? gm : (M - 1);
            int szA = (gm < M) ? 16 : 0;
            size_t aoff = (size_t)gmc * SP + k0 + ch * 8;
            cpa16(b + doff,            Ahg + aoff, szA);
            cpa16(b + ARRB + doff,     Alg + aoff, szA);
            size_t boff = (size_t)row * SP + k0 + ch * 8;
            cpa16(b + 2 * ARRB + doff, Bhg + boff, 16);
            cpa16(b + 3 * ARRB + doff, Blg + boff, 16);
        }
        asm volatile("cp.async.commit_group;");
    };

    issue(0, 0);

    for (int s = 0; s < steps; s++) {
        int buf = s & 1;
        if (s + 1 < steps) {
            issue(s + 1, buf ^ 1);
            asm volatile("cp.async.wait_group 1;");
        } else {
            asm volatile("cp.async.wait_group 0;");
        }
        __syncthreads();

        uint32_t base = sbase + buf * 4 * ARRB;
        uint32_t aAh = base +            ((wm * 64 + aRow) * KP + aCol8) * 2;
        uint32_t aAl = aAh + ARRB;
        uint32_t aBh = base + 2 * ARRB + ((wn * 32 + bRow) * KP + bCol8) * 2;
        uint32_t aBl = aBh + ARRB;

#pragma unroll
        for (int kk = 0; kk < 32; kk += 16) {
            uint32_t ah[4][4], al[4][4];
#pragma unroll
            for (int mf = 0; mf < 4; mf++) {
                uint32_t off = (mf * 16 * KP + kk) * 2;
                ldsm_x4(ah[mf], aAh + off);
                ldsm_x4(al[mf], aAl + off);
            }
#pragma unroll
            for (int nf = 0; nf < 4; nf++) {
                uint32_t off = (nf * 8 * KP + kk) * 2;
                uint32_t bh[2], bl[2];
                ldsm_x2(bh, aBh + off);
                ldsm_x2(bl, aBl + off);
                // term-major: consecutive MMAs hit different accumulators
#pragma unroll
                for (int mf = 0; mf < 4; mf++) mma_bf16(acc[mf][nf], ah[mf], bh);
#pragma unroll
                for (int mf = 0; mf < 4; mf++) mma_bf16(acc[mf][nf], ah[mf], bl);
#pragma unroll
                for (int mf = 0; mf < 4; mf++) mma_bf16(acc[mf][nf], al[mf], bh);
            }
        }
        __syncthreads();
    }

    // epilogue: write fp16 xw (halves gather-side read traffic)
#pragma unroll
    for (int mf = 0; mf < 4; mf++) {
#pragma unroll
        for (int nf = 0; nf < 4; nf++) {
            int gm = m_blk + wm * 64 + mf * 16 + lr;
            int c  = wn * 32 + nf * 8 + lc2;
            if (c < 100) {
                if (gm < M)
                    *(__half2*)(g_xwh + (size_t)gm * F + c) =
                        __floats2half2_rn(acc[mf][nf][0], acc[mf][nf][1]);
                if (gm + 8 < M)
                    *(__half2*)(g_xwh + (size_t)(gm + 8) * F + c) =
                        __floats2half2_rn(acc[mf][nf][2], acc[mf][nf][3]);
            }
        }
    }
}

// ---------------- fused GCN aggregation (CSR pull, fp16 xw reads) -------------
__global__ __launch_bounds__(256) void gather_kernel(const float* __restrict__ bias,
                                                     int fusePool) {
    int node = blockIdx.x * 8 + (threadIdx.x >> 5);
    int lane = threadIdx.x & 31;
    if (node >= NN) return;
    if (lane >= FC) {
        if (!fusePool && lane >= 25) {
            int pc = 100 + (lane - 25) * 4;
            uint2 z = make_uint2(0u, 0u);
            *(uint2*)&g_ah[(size_t)node * SPH + pc] = z;
            *(uint2*)&g_al[(size_t)node * SPH + pc] = z;
        }
        return;
    }
    int beg = g_off[node];
    int end = g_off[node + 1];

    float4 acc = make_float4(0.f, 0.f, 0.f, 0.f);
    int j = beg;
    for (; j + 1 < end; j += 2) {
        int   r0 = __ldg(&g_src[j]);
        float w0 = __ldg(&g_wt[j]);
        int   r1 = __ldg(&g_src[j + 1]);
        float w1 = __ldg(&g_wt[j + 1]);
        float4 v0 = ldxw4(r0, lane);
        float4 v1 = ldxw4(r1, lane);
        acc.x = fmaf(w0, v0.x, acc.x); acc.y = fmaf(w0, v0.y, acc.y);
        acc.z = fmaf(w0, v0.z, acc.z); acc.w = fmaf(w0, v0.w, acc.w);
        acc.x = fmaf(w1, v1.x, acc.x); acc.y = fmaf(w1, v1.y, acc.y);
        acc.z = fmaf(w1, v1.z, acc.z); acc.w = fmaf(w1, v1.w, acc.w);
    }
    if (j < end) {
        int   r0 = __ldg(&g_src[j]);
        float w0 = __ldg(&g_wt[j]);
        float4 v0 = ldxw4(r0, lane);
        acc.x = fmaf(w0, v0.x, acc.x); acc.y = fmaf(w0, v0.y, acc.y);
        acc.z = fmaf(w0, v0.z, acc.z); acc.w = fmaf(w0, v0.w, acc.w);
    }

    float sw = g_selfw[node];
    float4 xv = ldxw4(node, lane);
    float4 b  = __ldg(((const float4*)bias) + lane);
    float4 o;
    o.x = fmaxf(fmaf(sw, xv.x, acc.x) + b.x, 0.f);
    o.y = fmaxf(fmaf(sw, xv.y, acc.y) + b.y, 0.f);
    o.z = fmaxf(fmaf(sw, xv.z, acc.z) + b.z, 0.f);
    o.w = fmaxf(fmaf(sw, xv.w, acc.w) + b.w, 0.f);

    if (fusePool) {
        int g = g_batch[node];
        red4(((float4*)g_pool) + (g * FC + lane), o.x, o.y, o.z, o.w);
    } else {
        __nv_bfloat16 hx = __float2bfloat16(o.x);
        __nv_bfloat16 hy = __float2bfloat16(o.y);
        __nv_bfloat16 hz = __float2bfloat16(o.z);
        __nv_bfloat16 hw = __float2bfloat16(o.w);
        uint2 hv = make_uint2(pk2(hx, hy), pk2(hz, hw));
        uint2 lv = make_uint2(
            pk2(__float2bfloat16(o.x - __bfloat162float(hx)),
                __float2bfloat16(o.y - __bfloat162float(hy))),
            pk2(__float2bfloat16(o.z - __bfloat162float(hz)),
                __float2bfloat16(o.w - __bfloat162float(hw))));
        *(uint2*)&g_ah[(size_t)node * SPH + lane * 4] = hv;
        *(uint2*)&g_al[(size_t)node * SPH + lane * 4] = lv;
    }
}

// ---------------- MLP head (stage 0 applies mean division) ----------------
__global__ void mlp_kernel(const float* __restrict__ Wt, const float* __restrict__ bias,
                           float* __restrict__ outp, int stage, int Kd, int Nd, int doRelu)
{
    const float* A = (stage == 0) ? g_pool : (stage == 1) ? g_t1 : g_t2;
    float*       C = (stage == 0) ? g_t1   : (stage == 1) ? g_t2 : outp;
    __shared__ float arow[128];
    int g = blockIdx.x, j = threadIdx.x;
    if (j < Kd) {
        float v = A[g * Kd + j];
        if (stage == 0) v = v / fmaxf(g_cnt[g], 1.0f);
        arow[j] = v;
    }
    __syncthreads();
    if (j < Nd) {
        float s = bias[j];
        for (int k = 0; k < Kd; k++) s = fmaf(arow[k], Wt[k * Nd + j], s);
        if (doRelu) s = fmaxf(s, 0.f);
        C[g * Nd + j] = s;
    }
}

// ---------------- launch ----------------
extern "C" void kernel_launch(void* const* d_in, const int* in_sizes, int n_in,
                              void* d_out, int out_size)
{
    const float* x     = (const float*)d_in[0];
    const void*  ei    = d_in[1];
    const void*  batch = d_in[2];
    const float* Wc[5] = {(const float*)d_in[3], (const float*)d_in[5], (const float*)d_in[7],
                          (const float*)d_in[9], (const float*)d_in[11]};
    const float* Bc[5] = {(const float*)d_in[4], (const float*)d_in[6], (const float*)d_in[8],
                          (const float*)d_in[10], (const float*)d_in[12]};
    const float* Wl1 = (const float*)d_in[13];
    const float* bl1 = (const float*)d_in[14];
    const float* Wl2 = (const float*)d_in[15];
    const float* bl2 = (const float*)d_in[16];
    const float* Wl3 = (const float*)d_in[17];
    const float* bl3 = (const float*)d_in[18];
    float* out = (float*)d_out;

    const int TB = 256;
    const int GB = (NN + 127) / 128;     // 782
    const int SMEM = 8 * ARRB;           // 81920 bytes
    const int NBLK = (NN + 1023) / 1024; // 98

    cudaFuncSetAttribute(sgemm_kernel,
                         cudaFuncAttributeMaxDynamicSharedMemorySize, SMEM);

    // slots 0..2: split x, all W splits, detect (+zero-init)
    {
        size_t n = (size_t)NN * SP1;
        split_x_kernel<<<(unsigned)((n + TB - 1) / TB), TB>>>(x);
    }
    {
        dim3 wg((128 * SP1 + TB - 1) / TB, 5);
        wsplit_all_kernel<<<wg, TB>>>(Wc[0], Wc[1], Wc[2], Wc[3], Wc[4]);
    }
    detect_kernel<<<1, 512>>>((const int*)ei);

    // slot 3: layer-1 GEMM (ncu profiles launch #3)
    sgemm_kernel<<<GB, 256, SMEM>>>(0, NN, SP1);

    // graph preprocessing (coalesced scan)
    prep_deg_kernel<<<(NE + TB - 1) / TB, TB>>>(ei);
    prep_batch_kernel<<<(NN + TB - 1) / TB, TB>>>(batch);
    scan1_kernel<<<NBLK, 1024>>>();
    scan2_kernel<<<1, 128>>>(NBLK);
    scan3_kernel<<<NBLK, 1024>>>();
    fill_kernel<<<(NE + TB - 1) / TB, TB>>>();

    gather_kernel<<<(NN + 7) / 8, 256>>>(Bc[0], 0);

    for (int l = 1; l < 5; l++) {
        sgemm_kernel<<<GB, 256, SMEM>>>(l * WSLOT, NN, SPH);
        gather_kernel<<<(NN + 7) / 8, 256>>>(Bc[l], (l == 4) ? 1 : 0);
    }

    mlp_kernel<<<NG, 128>>>(Wl1, bl1, nullptr, 0, 100, 100, 1);
    mlp_kernel<<<NG, 128>>>(Wl2, bl2, nullptr, 1, 100, 100, 1);
    mlp_kernel<<<NG, 128>>>(Wl3, bl3, out, 2, 100, 29, 0);
}

// round 15
// speedup vs baseline: 1.4459x; 1.4459x over previous
#include <cuda_runtime.h>
#include <cuda_bf16.h>
#include <cstdint>

#define NN 100000
#define NE 1600000
#define NG 1000
#define F  100
#define FC 25     // float4 chunks per feature row
#define SP1 352   // padded K stride for layer-1 input (336 -> 352 = 11*32)
#define SPH 128   // padded K stride for hidden layers (100 -> 128 = 4*32)
#define KP  40    // smem k-stride (bf16 elems), conflict-free
#define ARRB (128 * KP * 2)   // bytes per smem array (10240)
#define WSLOT (128 * SP1)

// ---------------- scratch ----------------
__device__ __align__(16) float g_xw[(size_t)NN * F];
__device__ __align__(16) __nv_bfloat16 g_ah[(size_t)NN * SP1];
__device__ __align__(16) __nv_bfloat16 g_al[(size_t)NN * SP1];
__device__ __align__(16) __nv_bfloat16 g_bh[5 * 128 * SP1];
__device__ __align__(16) __nv_bfloat16 g_bl[5 * 128 * SP1];
__device__ int   g_degi[NN];
__device__ int   g_off[NN + 1];
__device__ int   g_cur[NN];
__device__ float g_dinv[NN];
__device__ float g_selfw[NN];
__device__ int   g_row[NE];
__device__ int   g_col[NE];
__device__ int   g_src[NE];
__device__ float g_wt[NE];
__device__ int   g_batch[NN];
__device__ __align__(16) float g_pool[NG * F];
__device__ float g_cnt[NG];
__device__ float g_t1[NG * F];
__device__ float g_t2[NG * F];
__device__ int   g_is64;
__device__ int   g_bsum[128];
__device__ int   g_bpre[128];

__device__ __forceinline__ void red4(float4* p, float x, float y, float z, float w) {
    asm volatile("red.global.add.v4.f32 [%0], {%1,%2,%3,%4};"
                 :: "l"(p), "f"(x), "f"(y), "f"(z), "f"(w) : "memory");
}

__device__ __forceinline__ uint32_t pk2(__nv_bfloat16 a, __nv_bfloat16 b) {
    union { __nv_bfloat162 v; uint32_t u; } c;
    c.v = __nv_bfloat162(a, b);
    return c.u;
}

// ---------------- bf16 split preprocessing (vectorized) ----------------
// one thread = one 4-elem chunk: float4 read, uint2 hi/lo writes
__global__ void split_x_kernel(const float* __restrict__ x) {
    int i = blockIdx.x * blockDim.x + threadIdx.x;     // chunk index
    if (i >= NN * (SP1 / 4)) return;
    int node = i / (SP1 / 4);
    int k4   = i - node * (SP1 / 4);                   // 0..87
    float4 v = make_float4(0.f, 0.f, 0.f, 0.f);
    if (k4 < 84)                                        // 84*4 = 336
        v = *(const float4*)(x + (size_t)node * 336 + k4 * 4);
    __nv_bfloat16 hx = __float2bfloat16(v.x);
    __nv_bfloat16 hy = __float2bfloat16(v.y);
    __nv_bfloat16 hz = __float2bfloat16(v.z);
    __nv_bfloat16 hw = __float2bfloat16(v.w);
    uint2 hv = make_uint2(pk2(hx, hy), pk2(hz, hw));
    uint2 lv = make_uint2(
        pk2(__float2bfloat16(v.x - __bfloat162float(hx)),
            __float2bfloat16(v.y - __bfloat162float(hy))),
        pk2(__float2bfloat16(v.z - __bfloat162float(hz)),
            __float2bfloat16(v.w - __bfloat162float(hw))));
    size_t o = (size_t)node * SP1 + k4 * 4;
    *(uint2*)&g_ah[o] = hv;
    *(uint2*)&g_al[o] = lv;
}

__global__ void wsplit_all_kernel(const float* __restrict__ W0, const float* __restrict__ W1,
                                  const float* __restrict__ W2, const float* __restrict__ W3,
                                  const float* __restrict__ W4) {
    int l = blockIdx.y;
    const float* W = (l == 0) ? W0 : (l == 1) ? W1 : (l == 2) ? W2 : (l == 3) ? W3 : W4;
    int SP = l ? SPH : SP1;
    int K  = l ? 100 : 336;
    int base = l * WSLOT;
    int i = blockIdx.x * blockDim.x + threadIdx.x;
    if (i >= 128 * SP) return;
    int n = i / SP;
    int k = i - n * SP;
    float v = (n < 100 && k < K) ? W[k * 100 + n] : 0.0f;
    __nv_bfloat16 hi = __float2bfloat16(v);
    g_bh[base + i] = hi;
    g_bl[base + i] = __float2bfloat16(v - __bfloat162float(hi));
}

// ---------------- dtype detection + zero-init fused ----------------
__global__ void detect_kernel(const int* __restrict__ ei32) {
    __shared__ int s;
    int t = threadIdx.x;
    if (t == 0) s = 0;
    __syncthreads();
    int v = ei32[t * 2 + 1] | ei32[2048 + t * 2 + 1] |
            ei32[4096 + t * 2 + 1] | ei32[6144 + t * 2 + 1];
    if (v) atomicOr(&s, 1);
    __syncthreads();
    if (t == 0) g_is64 = (s == 0) ? 1 : 0;
    for (int i = t; i < NN; i += 512) g_degi[i] = 0;
    for (int i = t; i < NG; i += 512) g_cnt[i] = 0.0f;
    for (int i = t; i < NG * FC; i += 512)
        ((float4*)g_pool)[i] = make_float4(0.f, 0.f, 0.f, 0.f);
}

// ---------------- graph preprocessing ----------------
__global__ void prep_deg_kernel(const void* __restrict__ ei) {
    int e = blockIdx.x * blockDim.x + threadIdx.x;
    if (e >= NE) return;
    int r, c;
    if (g_is64) {
        const long long* p = (const long long*)ei;
        r = (int)p[e];
        c = (int)p[NE + e];
    } else {
        const int* p = (const int*)ei;
        r = p[e];
        c = p[NE + e];
    }
    g_row[e] = r;
    g_col[e] = c;
    atomicAdd(&g_degi[c], 1);
}

__global__ void prep_batch_kernel(const void* __restrict__ batch) {
    int i = blockIdx.x * blockDim.x + threadIdx.x;
    if (i >= NN) return;
    int b;
    if (g_is64) b = (int)((const long long*)batch)[i];
    else        b = ((const int*)batch)[i];
    g_batch[i] = b;
    atomicAdd(&g_cnt[b], 1.0f);
}

// ---------------- coalesced 3-phase scan ----------------
__global__ void scan1_kernel() {
    __shared__ int red[32];
    int b = blockIdx.x, t = threadIdx.x;
    int idx = b * 1024 + t;
    int v = 0;
    if (idx < NN) {
        v = g_degi[idx];
        float d = (float)v + 2.0f;
        float r = rsqrtf(d);
        r = r * (1.5f - 0.5f * d * r * r);
        g_dinv[idx]  = r;
        g_selfw[idx] = 2.0f / d;
    }
    int s = v;
#pragma unroll
    for (int o = 16; o > 0; o >>= 1) s += __shfl_down_sync(~0u, s, o);
    if ((t & 31) == 0) red[t >> 5] = s;
    __syncthreads();
    if (t < 32) {
        int x = red[t];
#pragma unroll
        for (int o = 16; o > 0; o >>= 1) x += __shfl_down_sync(~0u, x, o);
        if (t == 0) g_bsum[b] = x;
    }
}

__global__ void scan2_kernel(int nblk) {
    int t = threadIdx.x;
    __shared__ int sh[128];
    int v = (t < nblk) ? g_bsum[t] : 0;
    sh[t] = v;
    __syncthreads();
    for (int o = 1; o < 128; o <<= 1) {
        int u = (t >= o) ? sh[t - o] : 0;
        __syncthreads();
        sh[t] += u;
        __syncthreads();
    }
    g_bpre[t] = sh[t] - v;
    if (t == 0) g_off[NN] = NE;
}

__global__ void scan3_kernel() {
    __shared__ int ws[32];
    int b = blockIdx.x, t = threadIdx.x;
    int idx = b * 1024 + t;
    int lane = t & 31, w = t >> 5;
    int v = (idx < NN) ? g_degi[idx] : 0;
    int s = v;
#pragma unroll
    for (int o = 1; o < 32; o <<= 1) {
        int u = __shfl_up_sync(~0u, s, o);
        if (lane >= o) s += u;
    }
    if (lane == 31) ws[w] = s;
    __syncthreads();
    if (t < 32) {
        int x = ws[t];
#pragma unroll
        for (int o = 1; o < 32; o <<= 1) {
            int u = __shfl_up_sync(~0u, x, o);
            if (t >= o) x += u;
        }
        ws[t] = x;
    }
    __syncthreads();
    if (idx < NN) {
        int excl = s - v + (w ? ws[w - 1] : 0) + g_bpre[b];
        g_off[idx] = excl;
        g_cur[idx] = excl;
    }
}

__global__ void fill_kernel() {
    int e = blockIdx.x * blockDim.x + threadIdx.x;
    if (e >= NE) return;
    int r = g_row[e];
    int c = g_col[e];
    int pos = atomicAdd(&g_cur[c], 1);
    g_src[pos] = r;
    g_wt[pos]  = g_dinv[r] * g_dinv[c];
}

// ---------------- tensor GEMM (bf16 split, cp.async x2, ldmatrix frags) -------
// R11-exact mainloop: do NOT reorder the 3 split-term MMAs (measured regression)
__device__ __forceinline__ void mma_bf16(float* d, const uint32_t* a, const uint32_t* b) {
    asm volatile(
        "mma.sync.aligned.m16n8k16.row.col.f32.bf16.bf16.f32 "
        "{%0,%1,%2,%3}, {%4,%5,%6,%7}, {%8,%9}, {%0,%1,%2,%3};"
        : "+f"(d[0]), "+f"(d[1]), "+f"(d[2]), "+f"(d[3])
        : "r"(a[0]), "r"(a[1]), "r"(a[2]), "r"(a[3]), "r"(b[0]), "r"(b[1]));
}

__device__ __forceinline__ void cpa16(uint32_t dst, const void* src, int sz) {
    asm volatile("cp.async.cg.shared.global [%0], [%1], 16, %2;"
                 :: "r"(dst), "l"(src), "r"(sz));
}

__device__ __forceinline__ void ldsm_x4(uint32_t* r, uint32_t addr) {
    asm volatile("ldmatrix.sync.aligned.m8n8.x4.shared.b16 {%0,%1,%2,%3}, [%4];"
                 : "=r"(r[0]), "=r"(r[1]), "=r"(r[2]), "=r"(r[3]) : "r"(addr));
}

__device__ __forceinline__ void ldsm_x2(uint32_t* r, uint32_t addr) {
    asm volatile("ldmatrix.sync.aligned.m8n8.x2.shared.b16 {%0,%1}, [%2];"
                 : "=r"(r[0]), "=r"(r[1]) : "r"(addr));
}

__global__ __launch_bounds__(256, 2) void sgemm_kernel(int wslot, int M, int SP)
{
    extern __shared__ __align__(16) char smem[];
    const __nv_bfloat16* __restrict__ Ahg = g_ah;
    const __nv_bfloat16* __restrict__ Alg = g_al;
    const __nv_bfloat16* __restrict__ Bhg = g_bh + wslot;
    const __nv_bfloat16* __restrict__ Blg = g_bl + wslot;

    const int steps = SP / 32;
    int t     = threadIdx.x;
    int m_blk = blockIdx.x * 128;
    int wid   = t >> 5, lane = t & 31;
    int wm    = wid >> 2;
    int wn    = wid & 3;
    int lr    = lane >> 2;
    int lc2   = (lane & 3) << 1;
    uint32_t sbase = (uint32_t)__cvta_generic_to_shared(smem);

    int aRow  = lane & 15;
    int aCol8 = (lane >> 4) << 3;
    int bRow  = lane & 7;
    int bCol8 = lane & 8;

    float acc[4][4][4];
#pragma unroll
    for (int i = 0; i < 4; i++)
#pragma unroll
        for (int j = 0; j < 4; j++)
#pragma unroll
            for (int q = 0; q < 4; q++) acc[i][j][q] = 0.0f;

    auto issue = [&](int s, int buf) {
        int k0 = s * 32;
        uint32_t b = sbase + buf * 4 * ARRB;
#pragma unroll
        for (int i = 0; i < 2; i++) {
            int c   = t + 256 * i;
            int row = c >> 2;
            int ch  = c & 3;
            uint32_t doff = row * (KP * 2) + ch * 16;
            int gm  = m_blk + row;
            int gmc = (gm < M) ? gm : (M - 1);
            int szA = (gm < M) ? 16 : 0;
            size_t aoff = (size_t)gmc * SP + k0 + ch * 8;
            cpa16(b + doff,            Ahg + aoff, szA);
            cpa16(b + ARRB + doff,     Alg + aoff, szA);
            size_t boff = (size_t)row * SP + k0 + ch * 8;
            cpa16(b + 2 * ARRB + doff, Bhg + boff, 16);
            cpa16(b + 3 * ARRB + doff, Blg + boff, 16);
        }
        asm volatile("cp.async.commit_group;");
    };

    issue(0, 0);

    for (int s = 0; s < steps; s++) {
        int buf = s & 1;
        if (s + 1 < steps) {
            issue(s + 1, buf ^ 1);
            asm volatile("cp.async.wait_group 1;");
        } else {
            asm volatile("cp.async.wait_group 0;");
        }
        __syncthreads();

        uint32_t base = sbase + buf * 4 * ARRB;
        uint32_t aAh = base +            ((wm * 64 + aRow) * KP + aCol8) * 2;
        uint32_t aAl = aAh + ARRB;
        uint32_t aBh = base + 2 * ARRB + ((wn * 32 + bRow) * KP + bCol8) * 2;
        uint32_t aBl = aBh + ARRB;

#pragma unroll
        for (int kk = 0; kk < 32; kk += 16) {
            uint32_t ah[4][4], al[4][4];
#pragma unroll
            for (int mf = 0; mf < 4; mf++) {
                uint32_t off = (mf * 16 * KP + kk) * 2;
                ldsm_x4(ah[mf], aAh + off);
                ldsm_x4(al[mf], aAl + off);
            }
#pragma unroll
            for (int nf = 0; nf < 4; nf++) {
                uint32_t off = (nf * 8 * KP + kk) * 2;
                uint32_t bh[2], bl[2];
                ldsm_x2(bh, aBh + off);
                ldsm_x2(bl, aBl + off);
#pragma unroll
                for (int mf = 0; mf < 4; mf++) {
                    mma_bf16(acc[mf][nf], ah[mf], bh);
                    mma_bf16(acc[mf][nf], ah[mf], bl);
                    mma_bf16(acc[mf][nf], al[mf], bh);
                }
            }
        }
        __syncthreads();
    }

#pragma unroll
    for (int mf = 0; mf < 4; mf++) {
#pragma unroll
        for (int nf = 0; nf < 4; nf++) {
            int gm = m_blk + wm * 64 + mf * 16 + lr;
            int c  = wn * 32 + nf * 8 + lc2;
            if (c < 100) {
                if (gm < M)
                    *(float2*)(g_xw + (size_t)gm * 100 + c) =
                        make_float2(acc[mf][nf][0], acc[mf][nf][1]);
                if (gm + 8 < M)
                    *(float2*)(g_xw + (size_t)(gm + 8) * 100 + c) =
                        make_float2(acc[mf][nf][2], acc[mf][nf][3]);
            }
        }
    }
}

// ---------------- fused GCN aggregation (CSR pull) ----------------
__global__ __launch_bounds__(256) void gather_kernel(const float* __restrict__ bias,
                                                     int fusePool) {
    int node = blockIdx.x * 8 + (threadIdx.x >> 5);
    int lane = threadIdx.x & 31;
    if (node >= NN) return;
    if (lane >= FC) {
        if (!fusePool && lane >= 25) {
            int pc = 100 + (lane - 25) * 4;
            uint2 z = make_uint2(0u, 0u);
            *(uint2*)&g_ah[(size_t)node * SPH + pc] = z;
            *(uint2*)&g_al[(size_t)node * SPH + pc] = z;
        }
        return;
    }
    int beg = g_off[node];
    int end = g_off[node + 1];
    const float4* xw4 = (const float4*)g_xw;

    float4 acc = make_float4(0.f, 0.f, 0.f, 0.f);
    int j = beg;
    for (; j + 1 < end; j += 2) {
        int   r0 = __ldg(&g_src[j]);
        float w0 = __ldg(&g_wt[j]);
        int   r1 = __ldg(&g_src[j + 1]);
        float w1 = __ldg(&g_wt[j + 1]);
        float4 v0 = xw4[r0 * FC + lane];
        float4 v1 = xw4[r1 * FC + lane];
        acc.x = fmaf(w0, v0.x, acc.x); acc.y = fmaf(w0, v0.y, acc.y);
        acc.z = fmaf(w0, v0.z, acc.z); acc.w = fmaf(w0, v0.w, acc.w);
        acc.x = fmaf(w1, v1.x, acc.x); acc.y = fmaf(w1, v1.y, acc.y);
        acc.z = fmaf(w1, v1.z, acc.z); acc.w = fmaf(w1, v1.w, acc.w);
    }
    if (j < end) {
        int   r0 = __ldg(&g_src[j]);
        float w0 = __ldg(&g_wt[j]);
        float4 v0 = xw4[r0 * FC + lane];
        acc.x = fmaf(w0, v0.x, acc.x); acc.y = fmaf(w0, v0.y, acc.y);
        acc.z = fmaf(w0, v0.z, acc.z); acc.w = fmaf(w0, v0.w, acc.w);
    }

    float sw = g_selfw[node];
    float4 xv = xw4[node * FC + lane];
    float4 b  = __ldg(((const float4*)bias) + lane);
    float4 o;
    o.x = fmaxf(fmaf(sw, xv.x, acc.x) + b.x, 0.f);
    o.y = fmaxf(fmaf(sw, xv.y, acc.y) + b.y, 0.f);
    o.z = fmaxf(fmaf(sw, xv.z, acc.z) + b.z, 0.f);
    o.w = fmaxf(fmaf(sw, xv.w, acc.w) + b.w, 0.f);

    if (fusePool) {
        int g = g_batch[node];
        red4(((float4*)g_pool) + (g * FC + lane), o.x, o.y, o.z, o.w);
    } else {
        __nv_bfloat16 hx = __float2bfloat16(o.x);
        __nv_bfloat16 hy = __float2bfloat16(o.y);
        __nv_bfloat16 hz = __float2bfloat16(o.z);
        __nv_bfloat16 hw = __float2bfloat16(o.w);
        uint2 hv = make_uint2(pk2(hx, hy), pk2(hz, hw));
        uint2 lv = make_uint2(
            pk2(__float2bfloat16(o.x - __bfloat162float(hx)),
                __float2bfloat16(o.y - __bfloat162float(hy))),
            pk2(__float2bfloat16(o.z - __bfloat162float(hz)),
                __float2bfloat16(o.w - __bfloat162float(hw))));
        *(uint2*)&g_ah[(size_t)node * SPH + lane * 4] = hv;
        *(uint2*)&g_al[(size_t)node * SPH + lane * 4] = lv;
    }
}

// ---------------- MLP head (stage 0 applies mean division) ----------------
__global__ void mlp_kernel(const float* __restrict__ Wt, const float* __restrict__ bias,
                           float* __restrict__ outp, int stage, int Kd, int Nd, int doRelu)
{
    const float* A = (stage == 0) ? g_pool : (stage == 1) ? g_t1 : g_t2;
    float*       C = (stage == 0) ? g_t1   : (stage == 1) ? g_t2 : outp;
    __shared__ float arow[128];
    int g = blockIdx.x, j = threadIdx.x;
    if (j < Kd) {
        float v = A[g * Kd + j];
        if (stage == 0) v = v / fmaxf(g_cnt[g], 1.0f);
        arow[j] = v;
    }
    __syncthreads();
    if (j < Nd) {
        float s = bias[j];
        for (int k = 0; k < Kd; k++) s = fmaf(arow[k], Wt[k * Nd + j], s);
        if (doRelu) s = fmaxf(s, 0.f);
        C[g * Nd + j] = s;
    }
}

// ---------------- launch ----------------
extern "C" void kernel_launch(void* const* d_in, const int* in_sizes, int n_in,
                              void* d_out, int out_size)
{
    const float* x     = (const float*)d_in[0];
    const void*  ei    = d_in[1];
    const void*  batch = d_in[2];
    const float* Wc[5] = {(const float*)d_in[3], (const float*)d_in[5], (const float*)d_in[7],
                          (const float*)d_in[9], (const float*)d_in[11]};
    const float* Bc[5] = {(const float*)d_in[4], (const float*)d_in[6], (const float*)d_in[8],
                          (const float*)d_in[10], (const float*)d_in[12]};
    const float* Wl1 = (const float*)d_in[13];
    const float* bl1 = (const float*)d_in[14];
    const float* Wl2 = (const float*)d_in[15];
    const float* bl2 = (const float*)d_in[16];
    const float* Wl3 = (const float*)d_in[17];
    const float* bl3 = (const float*)d_in[18];
    float* out = (float*)d_out;

    const int TB = 256;
    const int GB = (NN + 127) / 128;     // 782
    const int SMEM = 8 * ARRB;           // 81920 bytes
    const int NBLK = (NN + 1023) / 1024; // 98

    cudaFuncSetAttribute(sgemm_kernel,
                         cudaFuncAttributeMaxDynamicSharedMemorySize, SMEM);

    // slots 0..2: split x (vectorized), all W splits, detect (+zero-init)
    split_x_kernel<<<(NN * (SP1 / 4) + TB - 1) / TB, TB>>>(x);
    {
        dim3 wg((128 * SP1 + TB - 1) / TB, 5);
        wsplit_all_kernel<<<wg, TB>>>(Wc[0], Wc[1], Wc[2], Wc[3], Wc[4]);
    }
    detect_kernel<<<1, 512>>>((const int*)ei);

    // slot 3: layer-1 GEMM (ncu profiles launch #3)
    sgemm_kernel<<<GB, 256, SMEM>>>(0, NN, SP1);

    // graph preprocessing (coalesced scan)
    prep_deg_kernel<<<(NE + TB - 1) / TB, TB>>>(ei);
    prep_batch_kernel<<<(NN + TB - 1) / TB, TB>>>(batch);
    scan1_kernel<<<NBLK, 1024>>>();
    scan2_kernel<<<1, 128>>>(NBLK);
    scan3_kernel<<<NBLK, 1024>>>();
    fill_kernel<<<(NE + TB - 1) / TB, TB>>>();

    gather_kernel<<<(NN + 7) / 8, 256>>>(Bc[0], 0);

    for (int l = 1; l < 5; l++) {
        sgemm_kernel<<<GB, 256, SMEM>>>(l * WSLOT, NN, SPH);
        gather_kernel<<<(NN + 7) / 8, 256>>>(Bc[l], (l == 4) ? 1 : 0);
    }

    mlp_kernel<<<NG, 128>>>(Wl1, bl1, nullptr, 0, 100, 100, 1);
    mlp_kernel<<<NG, 128>>>(Wl2, bl2, nullptr, 1, 100, 100, 1);
    mlp_kernel<<<NG, 128>>>(Wl3, bl3, out, 2, 100, 29, 0);
}